// round 7
// baseline (speedup 1.0000x reference)
#include <cuda_runtime.h>
#include <cuda_bf16.h>

#define BB 64
#define NN 128
#define FF 4
#define HH 100
#define PP 8128   // NN*(NN-1)/2

// Scratch (device globals: allocation-free)
__device__ float g_M1[FF][HH];     // W1[0:4] @ W2
__device__ float g_M2[FF][HH];     // W1[4:8] @ W2
__device__ float g_c2[HH];         // b1 @ W2 + b2
__device__ float g_A2[BB*NN*HH];   // [b][n][d]  (c2 pre-folded in)
__device__ float g_B2[BB*HH*NN];   // [b][d][n]

// ---------------------------------------------------------------- K1: fold weights
__global__ void k_weights(const float* __restrict__ W1, const float* __restrict__ b1,
                          const float* __restrict__ W2, const float* __restrict__ b2) {
    int d = threadIdx.x;
    if (d >= HH) return;
    float m1[FF] = {0.f, 0.f, 0.f, 0.f};
    float m2[FF] = {0.f, 0.f, 0.f, 0.f};
    float c = 0.f;
    for (int k = 0; k < HH; ++k) {
        float w = W2[k * HH + d];
        #pragma unroll
        for (int f = 0; f < FF; ++f) {
            m1[f] = fmaf(W1[f * HH + k], w, m1[f]);
            m2[f] = fmaf(W1[(FF + f) * HH + k], w, m2[f]);
        }
        c = fmaf(b1[k], w, c);
    }
    #pragma unroll
    for (int f = 0; f < FF; ++f) { g_M1[f][d] = m1[f]; g_M2[f][d] = m2[f]; }
    g_c2[d] = c + b2[d];
}

// ---------------------------------------------------------------- K2: A2[b][n][d] (+c2)
__global__ void k_nodes_A(const float* __restrict__ x) {
    int t = blockIdx.x * blockDim.x + threadIdx.x;
    if (t >= BB * NN * HH) return;
    int d  = t % HH;
    int bn = t / HH;
    const float* xp = x + bn * FF;
    float a = g_c2[d];
    a = fmaf(xp[0], g_M1[0][d], a);
    a = fmaf(xp[1], g_M1[1][d], a);
    a = fmaf(xp[2], g_M1[2][d], a);
    a = fmaf(xp[3], g_M1[3][d], a);
    g_A2[t] = a;
}

// ---------------------------------------------------------------- K3: B2[b][d][n]
__global__ void k_nodes_B(const float* __restrict__ x) {
    int t = blockIdx.x * blockDim.x + threadIdx.x;
    if (t >= BB * NN * HH) return;
    int n = t % NN;
    int d = (t / NN) % HH;
    int b = t / (NN * HH);
    const float* xp = x + (b * NN + n) * FF;
    float v = xp[0] * g_M2[0][d];
    v = fmaf(xp[1], g_M2[1][d], v);
    v = fmaf(xp[2], g_M2[2][d], v);
    v = fmaf(xp[3], g_M2[3][d], v);
    g_B2[t] = v;
}

// ---------------------------------------------------------------- K4: pair kernel
// Warp-per-tile: 8 i1-rows x 32 i2-lanes. Per batch, strip j (J0=32j) has
// 4*(j+1) 8-row tiles whose top row is above the diagonal: 4+8+12+16 = 40 tiles.
__global__ void __launch_bounds__(256) k_pairs(const float* __restrict__ W3,
                                               const float* __restrict__ b3p,
                                               float* __restrict__ out) {
    int warp_gid = (blockIdx.x * blockDim.x + threadIdx.x) >> 5;
    int lane = threadIdx.x & 31;

    int b   = warp_gid / 40;
    int tix = warp_gid % 40;
    int j, I0;
    if (tix < 4)       { j = 0; I0 = tix * 8; }
    else if (tix < 12) { j = 1; I0 = (tix - 4) * 8; }
    else if (tix < 24) { j = 2; I0 = (tix - 12) * 8; }
    else               { j = 3; I0 = (tix - 24) * 8; }
    int J0 = j * 32;
    int i2 = J0 + lane;

    const float* A2 = g_A2 + (b * NN + I0) * HH;   // 8 rows, d-contiguous, c2 folded in
    const float* B2 = g_B2 + b * HH * NN;          // [d][n]
    float acc[8] = {0.f, 0.f, 0.f, 0.f, 0.f, 0.f, 0.f, 0.f};
    float b3 = b3p[0];

    for (int d0 = 0; d0 < HH; d0 += 4) {
        float4 a[8];
        #pragma unroll
        for (int r = 0; r < 8; ++r)
            a[r] = *(const float4*)(A2 + r * HH + d0);
        float4 w  = *(const float4*)(W3 + d0);
        float bv0 = B2[(d0 + 0) * NN + i2];
        float bv1 = B2[(d0 + 1) * NN + i2];
        float bv2 = B2[(d0 + 2) * NN + i2];
        float bv3 = B2[(d0 + 3) * NN + i2];

        #pragma unroll
        for (int r = 0; r < 8; ++r) {
            acc[r] = fmaf(fmaxf(a[r].x + bv0, 0.f), w.x, acc[r]);
            acc[r] = fmaf(fmaxf(a[r].y + bv1, 0.f), w.y, acc[r]);
            acc[r] = fmaf(fmaxf(a[r].z + bv2, 0.f), w.z, acc[r]);
            acc[r] = fmaf(fmaxf(a[r].w + bv3, 0.f), w.w, acc[r]);
        }
    }

    #pragma unroll
    for (int t = 0; t < 8; ++t) {
        int i1 = I0 + t;
        if (i1 < i2) {
            float z = acc[t] + b3;
            float s = 1.f / (1.f + __expf(-z));
            int p = i1 * (2 * NN - 1 - i1) / 2 + (i2 - i1 - 1);
            out[b * PP + p] = s;
        }
    }
}

// ---------------------------------------------------------------- launch
extern "C" void kernel_launch(void* const* d_in, const int* in_sizes, int n_in,
                              void* d_out, int out_size) {
    const float* x  = (const float*)d_in[0];
    // d_in[1] = in_hitnr (unused by reference)
    const float* W1 = (const float*)d_in[2];
    const float* b1 = (const float*)d_in[3];
    const float* W2 = (const float*)d_in[4];
    const float* b2 = (const float*)d_in[5];
    const float* W3 = (const float*)d_in[6];
    const float* b3 = (const float*)d_in[7];
    float* out = (float*)d_out;

    k_weights<<<1, 128>>>(W1, b1, W2, b2);

    int node_total = BB * NN * HH;            // 819200
    int node_grid  = (node_total + 255) / 256;
    k_nodes_A<<<node_grid, 256>>>(x);
    k_nodes_B<<<node_grid, 256>>>(x);

    // 64 batches * 40 tiles = 2560 warps; 8 warps per 256-thread block
    k_pairs<<<2560 / 8, 256>>>(W3, b3, out);
}

// round 8
// speedup vs baseline: 1.6745x; 1.6745x over previous
#include <cuda_runtime.h>
#include <cuda_bf16.h>

#define BB 64
#define NN 128
#define FF 4
#define HH 100
#define HHP 104          // padded row (104*4 = 416 bytes, 16B-aligned rows)
#define NQ 25            // HH/4 d-quads
#define PP 8128          // NN*(NN-1)/2

// Scratch (device globals: allocation-free)
__device__ __align__(16) float g_M1[FF][HHP];       // W1[0:4] @ W2
__device__ __align__(16) float g_M2[FF][HHP];       // W1[4:8] @ W2
__device__ __align__(16) float g_c2[HHP];           // b1 @ W2 + b2
__device__ __align__(16) float g_A2[BB*NN*HHP];     // [b][n][d]  (c2 folded in)
__device__ __align__(16) float g_B2q[BB*NQ*NN*4];   // [b][dq][n][4]

// ---------------------------------------------------------------- K1: fold weights (parallel over d, reduce over k)
__global__ void k_weights(const float* __restrict__ W1, const float* __restrict__ b1,
                          const float* __restrict__ W2, const float* __restrict__ b2) {
    int d = blockIdx.x;          // 0..HH-1
    int k = threadIdx.x;         // 0..127
    int lane = k & 31, wid = k >> 5;

    float v[9];
    #pragma unroll
    for (int i = 0; i < 9; ++i) v[i] = 0.f;
    if (k < HH) {
        float w = W2[k * HH + d];
        #pragma unroll
        for (int f = 0; f < FF; ++f) {
            v[f]     = W1[f * HH + k] * w;
            v[4 + f] = W1[(FF + f) * HH + k] * w;
        }
        v[8] = b1[k] * w;
    }
    #pragma unroll
    for (int off = 16; off >= 1; off >>= 1) {
        #pragma unroll
        for (int i = 0; i < 9; ++i)
            v[i] += __shfl_xor_sync(0xffffffffu, v[i], off);
    }
    __shared__ float red[4][9];
    if (lane == 0) {
        #pragma unroll
        for (int i = 0; i < 9; ++i) red[wid][i] = v[i];
    }
    __syncthreads();
    if (k == 0) {
        float s[9];
        #pragma unroll
        for (int i = 0; i < 9; ++i)
            s[i] = red[0][i] + red[1][i] + red[2][i] + red[3][i];
        #pragma unroll
        for (int f = 0; f < FF; ++f) { g_M1[f][d] = s[f]; g_M2[f][d] = s[4 + f]; }
        g_c2[d] = s[8] + b2[d];
    }
}

// ---------------------------------------------------------------- K2: fused node transform
// thread = (b, dq, n), n fastest. Writes A2[b][n][dq*4..+3] and B2q[b][dq][n].
__global__ void k_nodes(const float* __restrict__ x) {
    int t = blockIdx.x * blockDim.x + threadIdx.x;
    if (t >= BB * NQ * NN) return;
    int n  = t & (NN - 1);
    int dq = (t / NN) % NQ;
    int b  = t / (NN * NQ);
    int d0 = dq * 4;

    float4 xv = *(const float4*)(x + (b * NN + n) * FF);
    float4 c  = *(const float4*)(g_c2 + d0);
    float4 a = c, v = make_float4(0.f, 0.f, 0.f, 0.f);
    #pragma unroll
    for (int f = 0; f < FF; ++f) {
        float xf = (f == 0) ? xv.x : (f == 1) ? xv.y : (f == 2) ? xv.z : xv.w;
        float4 m1 = *(const float4*)(&g_M1[f][d0]);
        float4 m2 = *(const float4*)(&g_M2[f][d0]);
        a.x = fmaf(xf, m1.x, a.x); a.y = fmaf(xf, m1.y, a.y);
        a.z = fmaf(xf, m1.z, a.z); a.w = fmaf(xf, m1.w, a.w);
        v.x = fmaf(xf, m2.x, v.x); v.y = fmaf(xf, m2.y, v.y);
        v.z = fmaf(xf, m2.z, v.z); v.w = fmaf(xf, m2.w, v.w);
    }
    *(float4*)(g_A2 + (b * NN + n) * HHP + d0) = a;
    *(float4*)(g_B2q + ((b * NQ + dq) * NN + n) * 4) = v;
}

// ---------------------------------------------------------------- K3: pair kernel
// Warp-per-tile: 4 i1-rows x 32 i2-lanes; 80 tiles per batch.
__global__ void __launch_bounds__(128) k_pairs(const float* __restrict__ W3,
                                               const float* __restrict__ b3p,
                                               float* __restrict__ out) {
    int warp_gid = (blockIdx.x * blockDim.x + threadIdx.x) >> 5;
    int lane = threadIdx.x & 31;

    int b   = warp_gid / 80;
    int tix = warp_gid % 80;
    int j, I0;
    if (tix < 8)       { j = 0; I0 = tix * 4; }
    else if (tix < 24) { j = 1; I0 = (tix - 8) * 4; }
    else if (tix < 48) { j = 2; I0 = (tix - 24) * 4; }
    else               { j = 3; I0 = (tix - 48) * 4; }
    int J0 = j * 32;
    int i2 = J0 + lane;

    const float* A2 = g_A2 + (b * NN + I0) * HHP;                 // 4 rows, c2 folded
    const float4* B2 = (const float4*)(g_B2q + (b * NQ * NN + i2) * 4);  // + q*NN*... lane quad
    float acc[4] = {0.f, 0.f, 0.f, 0.f};
    float b3 = b3p[0];

    #pragma unroll 5
    for (int q = 0; q < NQ; ++q) {
        int d0 = q * 4;
        float4 a0 = *(const float4*)(A2 + 0 * HHP + d0);
        float4 a1 = *(const float4*)(A2 + 1 * HHP + d0);
        float4 a2 = *(const float4*)(A2 + 2 * HHP + d0);
        float4 a3 = *(const float4*)(A2 + 3 * HHP + d0);
        float4 w  = *(const float4*)(W3 + d0);
        float4 bq = B2[q * NN];

        acc[0] = fmaf(fmaxf(a0.x + bq.x, 0.f), w.x, acc[0]);
        acc[1] = fmaf(fmaxf(a1.x + bq.x, 0.f), w.x, acc[1]);
        acc[2] = fmaf(fmaxf(a2.x + bq.x, 0.f), w.x, acc[2]);
        acc[3] = fmaf(fmaxf(a3.x + bq.x, 0.f), w.x, acc[3]);

        acc[0] = fmaf(fmaxf(a0.y + bq.y, 0.f), w.y, acc[0]);
        acc[1] = fmaf(fmaxf(a1.y + bq.y, 0.f), w.y, acc[1]);
        acc[2] = fmaf(fmaxf(a2.y + bq.y, 0.f), w.y, acc[2]);
        acc[3] = fmaf(fmaxf(a3.y + bq.y, 0.f), w.y, acc[3]);

        acc[0] = fmaf(fmaxf(a0.z + bq.z, 0.f), w.z, acc[0]);
        acc[1] = fmaf(fmaxf(a1.z + bq.z, 0.f), w.z, acc[1]);
        acc[2] = fmaf(fmaxf(a2.z + bq.z, 0.f), w.z, acc[2]);
        acc[3] = fmaf(fmaxf(a3.z + bq.z, 0.f), w.z, acc[3]);

        acc[0] = fmaf(fmaxf(a0.w + bq.w, 0.f), w.w, acc[0]);
        acc[1] = fmaf(fmaxf(a1.w + bq.w, 0.f), w.w, acc[1]);
        acc[2] = fmaf(fmaxf(a2.w + bq.w, 0.f), w.w, acc[2]);
        acc[3] = fmaf(fmaxf(a3.w + bq.w, 0.f), w.w, acc[3]);
    }

    #pragma unroll
    for (int t = 0; t < 4; ++t) {
        int i1 = I0 + t;
        if (i1 < i2) {
            float z = acc[t] + b3;
            float s = 1.f / (1.f + __expf(-z));
            int p = i1 * (2 * NN - 1 - i1) / 2 + (i2 - i1 - 1);
            out[b * PP + p] = s;
        }
    }
}

// ---------------------------------------------------------------- launch
extern "C" void kernel_launch(void* const* d_in, const int* in_sizes, int n_in,
                              void* d_out, int out_size) {
    const float* x  = (const float*)d_in[0];
    // d_in[1] = in_hitnr (unused by reference)
    const float* W1 = (const float*)d_in[2];
    const float* b1 = (const float*)d_in[3];
    const float* W2 = (const float*)d_in[4];
    const float* b2 = (const float*)d_in[5];
    const float* W3 = (const float*)d_in[6];
    const float* b3 = (const float*)d_in[7];
    float* out = (float*)d_out;

    k_weights<<<HH, 128>>>(W1, b1, W2, b2);

    int node_total = BB * NQ * NN;            // 204800
    k_nodes<<<(node_total + 255) / 256, 256>>>(x);

    // 64 batches * 80 tiles = 5120 warps; 4 warps per 128-thread block
    k_pairs<<<5120 / 4, 128>>>(W3, b3, out);
}